// round 13
// baseline (speedup 1.0000x reference)
#include <cuda_runtime.h>
#include <cuda_fp16.h>
#include <cstdint>
#include <math.h>

#define Bb 128
#define Tt 64
#define Ff 2048
#define Cc 22
#define Dd 8
#define Rr 8192
#define G4 8192
typedef __half fp16;

static __device__ float g_h [(size_t)Rr*Ff];
static __device__ float g_c [(size_t)Rr*Ff];
static __device__ float g_P [(size_t)Rr*G4];
static __device__ float g_fut[(size_t)Rr*Cc];
static __device__ float g_eh[(size_t)Bb*Ff];
static __device__ float g_ec[(size_t)Bb*Ff];
static __device__ float g_dbias[G4], g_ebias[G4];
static __device__ float g_Wtd[Cc*G4], g_Wte[Cc*G4];
static __device__ fp16 g_hh0[(size_t)Rr*Ff];
static __device__ fp16 g_hh1[(size_t)Rr*Ff];
static __device__ fp16 g_xh [(size_t)Rr*Ff];
static __device__ fp16 g_eh0[(size_t)Bb*Ff];
static __device__ fp16 g_eh1[(size_t)Bb*Ff];
static __device__ fp16 g_Wd[(size_t)G4*Ff];
static __device__ fp16 g_Wi[(size_t)G4*Ff];
static __device__ fp16 g_Wh[(size_t)G4*Ff];

__device__ __forceinline__ void mma_fp16(float* c, const unsigned* a, unsigned b0, unsigned b1) {
    asm volatile(
        "mma.sync.aligned.m16n8k16.row.col.f32.f16.f16.f32 "
        "{%0,%1,%2,%3}, {%4,%5,%6,%7}, {%8,%9}, {%0,%1,%2,%3};\n"
        : "+f"(c[0]), "+f"(c[1]), "+f"(c[2]), "+f"(c[3])
        : "r"(a[0]), "r"(a[1]), "r"(a[2]), "r"(a[3]), "r"(b0), "r"(b1));
}
__device__ __forceinline__ void ldsm4(unsigned* r, unsigned addr) {
    asm volatile("ldmatrix.sync.aligned.m8n8.x4.shared.b16 {%0,%1,%2,%3}, [%4];\n"
                 : "=r"(r[0]), "=r"(r[1]), "=r"(r[2]), "=r"(r[3]) : "r"(addr));
}
__device__ __forceinline__ void cp16(unsigned s, const void* g) {
    asm volatile("cp.async.cg.shared.global [%0],[%1],16;" :: "r"(s), "l"(g));
}
__device__ __forceinline__ float sigm(float x) { return 1.f / (1.f + __expf(-x)); }

// ---- legacy-MMA fp16 GEMM: C = Ah[128/CTA,K] @ Bh[BN,K]^T  (fp32 acc)
//      NWM warp-rows (warp tile (128/NWM) x 64), NWN = BN/64 warp-cols.
//      4-stage cp.async. epilogue: + bias + fut@Wt + Cin, then LSTM or store.
template<int BN, int NWM, bool LSTM>
__global__ void __launch_bounds__(32 * NWM * (BN / 64), 1)
gemm_leg(const fp16* __restrict__ Ah,
         const fp16* __restrict__ Bh, int K,
         const float* __restrict__ bias, const float* __restrict__ Wt, int Ntot,
         const float* __restrict__ fut,
         const float* __restrict__ Cin, long long ldcin,
         float* __restrict__ Cout, long long ldc,
         float* __restrict__ stc, float* __restrict__ sth,
         fp16* __restrict__ sthi)
{
    constexpr int NWN = BN / 64;                // warps along N
    constexpr int NT  = 32 * NWM * NWN;         // threads
    constexpr int MF  = 8 / NWM;                // 16-row m-fragments per warp
    constexpr int AST = 128 * 40;               // A elems per stage
    constexpr int BST = BN * 40;
    constexpr int STGB = (AST + BST) * 2;       // stage bytes
    constexpr int NCH  = 512 + 4 * BN;          // 16B chunks per stage

    extern __shared__ char dsm[];
    unsigned sb = (unsigned)__cvta_generic_to_shared(dsm);
    const int bm = blockIdx.y * 128, bn = blockIdx.x * BN;
    const int tid = threadIdx.x, warp = tid >> 5, lane = tid & 31;
    const int wm = (warp / NWN) * (16 * MF), wn = (warp % NWN) * 64;

    auto load = [&](int buf, int kt) {
        unsigned so = sb + buf * STGB;
        int k0 = kt * 32;
#pragma unroll
        for (int e = tid; e < NCH; e += NT) {
            const fp16* s; unsigned ro; int ci, base;
            if (e < 512) { s = Ah; ro = 0;       ci = e;       base = bm; }
            else         { s = Bh; ro = AST * 2; ci = e - 512; base = bn; }
            int row = ci >> 2, kc = ci & 3;
            cp16(so + ro + (unsigned)(row * 80 + kc * 16),
                 s + (size_t)(base + row) * K + k0 + kc * 8);
        }
        asm volatile("cp.async.commit_group;" ::: "memory");
    };

    float acc[MF][8][4];
#pragma unroll
    for (int i = 0; i < MF; i++)
#pragma unroll
        for (int j = 0; j < 8; j++)
#pragma unroll
            for (int e = 0; e < 4; e++) acc[i][j][e] = 0.f;

    const int T = K / 32;
    load(0, 0); load(1, 1); load(2, 2);

    for (int it = 0; it < T; ++it) {
        int rem = T - it;
        if (rem >= 3)      asm volatile("cp.async.wait_group 2;" ::: "memory");
        else if (rem == 2) asm volatile("cp.async.wait_group 1;" ::: "memory");
        else               asm volatile("cp.async.wait_group 0;" ::: "memory");
        __syncthreads();
        unsigned so = sb + (it & 3) * STGB;
#pragma unroll
        for (int ks = 0; ks < 2; ++ks) {
            const int kb = ks * 16;
            unsigned ah[MF][4], bh[8][2];
            const unsigned ak = (unsigned)((kb + ((lane & 16) ? 8 : 0)) * 2);
#pragma unroll
            for (int mf = 0; mf < MF; ++mf) {
                unsigned ad = so + (unsigned)((wm + mf * 16 + (lane & 15)) * 80) + ak;
                ldsm4(ah[mf], ad);
            }
            const unsigned brow = (unsigned)(((lane & 16) ? 8 : 0) + (lane & 7));
            const unsigned bk = (unsigned)((kb + ((lane & 8) ? 8 : 0)) * 2);
#pragma unroll
            for (int pp = 0; pp < 4; ++pp) {
                unsigned r[4];
                unsigned bd = so + AST * 2 + (unsigned)((wn + pp * 16 + brow) * 80) + bk;
                ldsm4(r, bd);
                bh[2*pp][0] = r[0];   bh[2*pp][1] = r[1];
                bh[2*pp+1][0] = r[2]; bh[2*pp+1][1] = r[3];
            }
#pragma unroll
            for (int mf = 0; mf < MF; ++mf)
#pragma unroll
                for (int nf = 0; nf < 8; ++nf)
                    mma_fp16(acc[mf][nf], ah[mf], bh[nf][0], bh[nf][1]);
        }
        if (it + 3 < T) load((it + 3) & 3, it + 3);
    }
    __syncthreads();

    // ---- epilogue: stage bias / Wt / fut into smem (overwrites stage bufs) ----
    float* bias_s = (float*)dsm;
    float* Wt_s   = bias_s + BN;
    float* fut_s  = Wt_s + Cc * BN;
    const bool wt = (Wt != nullptr);
    if (bias) for (int e = tid; e < BN; e += NT) bias_s[e] = bias[bn + e];
    if (wt) {
        for (int e = tid; e < Cc * BN; e += NT)
            Wt_s[e] = Wt[(size_t)(e / BN) * Ntot + bn + (e % BN)];
        for (int e = tid; e < 128 * Cc; e += NT)
            fut_s[e] = fut[(size_t)(bm + e / Cc) * Cc + (e % Cc)];
    }
    __syncthreads();

    const int c = lane & 3;
#pragma unroll
    for (int mf = 0; mf < MF; ++mf) {
        const int r0 = wm + mf * 16 + (lane >> 2);
        const long long rg0 = bm + r0;
#pragma unroll
        for (int nb = 0; nb < 8; ++nb) {
            const int cl = wn + nb * 8 + 2 * c;
            float* v = acc[mf][nb];
            if (bias) { float b0 = bias_s[cl], b1 = bias_s[cl+1]; v[0]+=b0; v[1]+=b1; v[2]+=b0; v[3]+=b1; }
            if (wt) {
#pragma unroll 1
                for (int k = 0; k < Cc; ++k) {
                    float w0 = Wt_s[k*BN+cl], w1 = Wt_s[k*BN+cl+1];
                    float fA = fut_s[r0*Cc+k], fB = fut_s[(r0+8)*Cc+k];
                    v[0] += fA*w0; v[1] += fA*w1; v[2] += fB*w0; v[3] += fB*w1;
                }
            }
            if (Cin) {
                float2 a0 = *(const float2*)(Cin + rg0*ldcin + bn + cl);
                float2 a1 = *(const float2*)(Cin + (rg0+8)*ldcin + bn + cl);
                v[0] += a0.x; v[1] += a0.y; v[2] += a1.x; v[3] += a1.y;
            }
            if (!LSTM) {
                *(float2*)(Cout + rg0*ldc + bn + cl)     = make_float2(v[0], v[1]);
                *(float2*)(Cout + (rg0+8)*ldc + bn + cl) = make_float2(v[2], v[3]);
            }
        }
        if (LSTM) {
#pragma unroll
            for (int q = 0; q < 4; ++q) {
                const int j = (((bn + wn + q*16) >> 4) << 2) + c;
#pragma unroll
                for (int e = 0; e < 2; ++e) {
                    long long rr = rg0 + e * 8;
                    float gi = acc[mf][2*q][2*e], gf = acc[mf][2*q][2*e+1];
                    float gg = acc[mf][2*q+1][2*e], go = acc[mf][2*q+1][2*e+1];
                    long long idx = rr * 2048 + j;
                    float cn = sigm(gf) * stc[idx] + sigm(gi) * tanhf(gg);
                    stc[idx] = cn;
                    float hv = sigm(go) * tanhf(cn);
                    sth[idx] = hv;
                    sthi[idx] = __float2half_rn(hv);
                }
            }
        }
    }
}

// ---- prep: natural -> gate-interleaved order ------------------------------
// within each 16-col group: i0 f0 i1 f1 i2 f2 i3 f3 g0 o0 g1 o1 g2 o2 g3 o3
__device__ __forceinline__ void imap(int n, int& gate, int& j) {
    int pos = n & 15, cc = (pos & 7) >> 1;
    gate = (pos < 8) ? (pos & 1) : (2 + (pos & 1));
    j = ((n >> 4) << 2) + cc;
}
__global__ void prep_iW(const float* __restrict__ W, int ldw, int Kd,
                        fp16* __restrict__ o)
{
    size_t total = (size_t)G4 * Kd;
    for (size_t i = blockIdx.x * (size_t)blockDim.x + threadIdx.x; i < total;
         i += (size_t)gridDim.x * blockDim.x) {
        int n = (int)(i / Kd), k = (int)(i - (size_t)n * Kd);
        int gate, j; imap(n, gate, j);
        o[i] = __float2half_rn(W[(size_t)(gate * 2048 + j) * ldw + k]);
    }
}
__global__ void prep_bias(const float* __restrict__ a, const float* __restrict__ b,
                          float* __restrict__ o)
{
    int n = blockIdx.x * blockDim.x + threadIdx.x;
    if (n >= G4) return;
    int gate, j; imap(n, gate, j);
    o[n] = a[gate * 2048 + j] + b[gate * 2048 + j];
}
__global__ void prep_Wt(const float* __restrict__ W, int ldw, int col0,
                        float* __restrict__ Wt)
{
    for (int i = blockIdx.x * blockDim.x + threadIdx.x; i < Cc * G4;
         i += gridDim.x * blockDim.x) {
        int k = i / G4, n = i - k * G4;
        int gate, j; imap(n, gate, j);
        Wt[i] = W[(size_t)(gate * 2048 + j) * ldw + col0 + k];
    }
}
__global__ void cvt_plain(const float* __restrict__ s, fp16* __restrict__ o, size_t n)
{
    for (size_t i = blockIdx.x * (size_t)blockDim.x + threadIdx.x; i < n;
         i += (size_t)gridDim.x * blockDim.x)
        o[i] = __float2half_rn(s[i]);
}

// ---- fut = h@trW^T + trb; also writes dec_scores[:, :, d, :] ----
__global__ void skinny_fut(const float* __restrict__ h, const float* __restrict__ trW,
                           const float* __restrict__ trb, float* __restrict__ fut,
                           float* __restrict__ outdec, int d)
{
    int warp = threadIdx.x >> 5, lane = threadIdx.x & 31;
    int r = blockIdx.x * 8 + warp;
    const float4* hr = (const float4*)(h + (size_t)r * 2048);
    float4 hv[16];
#pragma unroll
    for (int i = 0; i < 16; ++i) hv[i] = hr[i * 32 + lane];
#pragma unroll 1
    for (int n = 0; n < Cc; ++n) {
        const float4* wr = (const float4*)(trW + (size_t)n * 2048);
        float s = 0.f;
#pragma unroll
        for (int i = 0; i < 16; ++i) {
            float4 w = wr[i * 32 + lane];
            s += hv[i].x * w.x + hv[i].y * w.y + hv[i].z * w.z + hv[i].w * w.w;
        }
#pragma unroll
        for (int o = 16; o; o >>= 1) s += __shfl_down_sync(0xffffffffu, s, o);
        if (lane == 0) {
            float val = s + trb[n];
            fut[(size_t)r * Cc + n] = val;
            outdec[((size_t)r * Dd + d) * Cc + n] = val;
        }
    }
}
__global__ void cls_skinny(const float* __restrict__ eh, const float* __restrict__ W,
                           const float* __restrict__ b, float* __restrict__ out, int t)
{
    int w = (int)((blockIdx.x * (long long)blockDim.x + threadIdx.x) >> 5);
    int lane = threadIdx.x & 31;
    if (w >= Bb * Cc) return;
    int m = w / Cc, n = w - m * Cc;
    const float4* a = (const float4*)(eh + (size_t)m * 2048);
    const float4* ww = (const float4*)(W + (size_t)n * 2048);
    float s = 0.f;
#pragma unroll
    for (int i = 0; i < 16; ++i) {
        float4 av = a[i * 32 + lane], wv = ww[i * 32 + lane];
        s += av.x * wv.x + av.y * wv.y + av.z * wv.z + av.w * wv.w;
    }
#pragma unroll
    for (int o = 16; o; o >>= 1) s += __shfl_down_sync(0xffffffffu, s, o);
    if (lane == 0) out[((size_t)m * Tt + t) * Cc + n] = s + b[n];
}

extern "C" void kernel_launch(void* const* d_in, const int* in_sizes, int n_in,
                              void* d_out, int out_size)
{
    const float* x       = (const float*)d_in[0];
    const float* dec_Wih = (const float*)d_in[1];
    const float* dec_Whh = (const float*)d_in[2];
    const float* dec_bih = (const float*)d_in[3];
    const float* dec_bhh = (const float*)d_in[4];
    const float* tr_W    = (const float*)d_in[5];
    const float* tr_b    = (const float*)d_in[6];
    const float* enc_Wih = (const float*)d_in[7];
    const float* enc_Whh = (const float*)d_in[8];
    const float* enc_bih = (const float*)d_in[9];
    const float* enc_bhh = (const float*)d_in[10];
    const float* cls_W   = (const float*)d_in[11];
    const float* cls_b   = (const float*)d_in[12];
    float* out     = (float*)d_out;
    float* out_dec = out + (size_t)Bb * Tt * Cc;

    float *h, *c, *P, *fut, *eh, *ec, *dbias, *ebias, *Wtd, *Wte;
    fp16 *hh0, *hh1, *xh, *eh0, *eh1, *Wd, *Wi, *Wh;
    cudaGetSymbolAddress((void**)&h, g_h);     cudaGetSymbolAddress((void**)&c, g_c);
    cudaGetSymbolAddress((void**)&P, g_P);     cudaGetSymbolAddress((void**)&fut, g_fut);
    cudaGetSymbolAddress((void**)&eh, g_eh);   cudaGetSymbolAddress((void**)&ec, g_ec);
    cudaGetSymbolAddress((void**)&dbias, g_dbias); cudaGetSymbolAddress((void**)&ebias, g_ebias);
    cudaGetSymbolAddress((void**)&Wtd, g_Wtd); cudaGetSymbolAddress((void**)&Wte, g_Wte);
    cudaGetSymbolAddress((void**)&hh0, g_hh0); cudaGetSymbolAddress((void**)&hh1, g_hh1);
    cudaGetSymbolAddress((void**)&xh, g_xh);
    cudaGetSymbolAddress((void**)&eh0, g_eh0); cudaGetSymbolAddress((void**)&eh1, g_eh1);
    cudaGetSymbolAddress((void**)&Wd, g_Wd);   cudaGetSymbolAddress((void**)&Wi, g_Wi);
    cudaGetSymbolAddress((void**)&Wh, g_Wh);

    const int SMB = 4 * (128 * 40 + 256 * 40) * 2;   // 122880 (BN=256)
    const int SMS = 4 * (128 * 40 + 64 * 40) * 2;    // 61440 (BN=64)
    cudaFuncSetAttribute((const void*)gemm_leg<256, 2, true>,
                         cudaFuncAttributeMaxDynamicSharedMemorySize, SMB);
    cudaFuncSetAttribute((const void*)gemm_leg<256, 2, false>,
                         cudaFuncAttributeMaxDynamicSharedMemorySize, SMB);
    cudaFuncSetAttribute((const void*)gemm_leg<64, 4, true>,
                         cudaFuncAttributeMaxDynamicSharedMemorySize, SMS);

    cudaMemsetAsync(c,   0, sizeof(float) * (size_t)Rr * Ff, 0);
    cudaMemsetAsync(ec,  0, sizeof(float) * (size_t)Bb * Ff, 0);
    cudaMemsetAsync(eh0, 0, 2 * (size_t)Bb * Ff, 0);

    prep_bias<<<G4 / 256, 256>>>(dec_bih, dec_bhh, dbias);
    prep_bias<<<G4 / 256, 256>>>(enc_bih, enc_bhh, ebias);
    prep_Wt<<<704, 256>>>(dec_Wih, Cc, 0, Wtd);
    prep_Wt<<<704, 256>>>(enc_Wih, Ff + Cc, Ff, Wte);
    prep_iW<<<8192, 256>>>(dec_Whh, Ff, Ff, Wd);
    prep_iW<<<8192, 256>>>(enc_Whh, Ff, Ff, Wh);
    prep_iW<<<8192, 256>>>(enc_Wih, Ff + Cc, Ff, Wi);
    cvt_plain<<<8192, 256>>>(x, xh, (size_t)Rr * Ff);

    fp16* HH[2] = {hh0, hh1};

    // ---- Phase 1: 8 batched decoder steps (R=8192 rows) ----
    for (int d = 0; d < Dd; d++) {
        const fp16* Ahh = (d == 0) ? xh : HH[(d - 1) & 1];
        gemm_leg<256, 2, true><<<dim3(32, 64), 256, SMB>>>(
            Ahh, Wd, Ff,
            dbias, (d == 0) ? nullptr : Wtd, G4, fut,
            nullptr, 0, nullptr, 0,
            c, h, HH[d & 1]);
        skinny_fut<<<Rr / 8, 256>>>(h, tr_W, tr_b, fut, out_dec, d);
    }

    // ---- Phase 2: P = [x | fut] @ enc_Wih^T + ebias (interleaved cols) ----
    gemm_leg<256, 2, false><<<dim3(32, 64), 256, SMB>>>(
        xh, Wi, Ff,
        ebias, Wte, G4, fut,
        nullptr, 0, P, (long long)G4,
        nullptr, nullptr, nullptr);

    fp16* EH[2] = {eh0, eh1};

    // ---- Phase 3: sequential encoder over T=64 ----
    for (int t = 0; t < Tt; t++) {
        gemm_leg<64, 4, true><<<dim3(128, 1), 128, SMS>>>(
            EH[t & 1], Wh, Ff,
            nullptr, nullptr, G4, nullptr,
            P + (size_t)t * G4, (long long)Tt * G4,
            nullptr, 0,
            ec, eh, EH[(t + 1) & 1]);
        cls_skinny<<<(Bb * Cc * 32 + 255) / 256, 256>>>(eh, cls_W, cls_b, out, t);
    }
}

// round 14
// speedup vs baseline: 1.1148x; 1.1148x over previous
#include <cuda_runtime.h>
#include <cuda_fp16.h>
#include <cstdint>
#include <math.h>

#define Bb 128
#define Tt 64
#define Ff 2048
#define Cc 22
#define Dd 8
#define Rr 8192
#define G4 8192
typedef __half fp16;

static __device__ float g_h [(size_t)Rr*Ff];
static __device__ float g_c [(size_t)Rr*Ff];
static __device__ float g_P [(size_t)Rr*G4];
static __device__ float g_fut[(size_t)Rr*Cc];
static __device__ float g_eh[(size_t)Bb*Ff];
static __device__ float g_ec[(size_t)Bb*Ff];
static __device__ float g_dbias[G4], g_ebias[G4];
static __device__ float g_Wtd[Cc*G4], g_Wte[Cc*G4];
static __device__ fp16 g_hh0[(size_t)Rr*Ff];
static __device__ fp16 g_hh1[(size_t)Rr*Ff];
static __device__ fp16 g_xh [(size_t)Rr*Ff];
static __device__ fp16 g_eh0[(size_t)Bb*Ff];
static __device__ fp16 g_eh1[(size_t)Bb*Ff];
static __device__ fp16 g_Wd[(size_t)G4*Ff];
static __device__ fp16 g_Wi[(size_t)G4*Ff];
static __device__ fp16 g_Wh[(size_t)G4*Ff];

__device__ __forceinline__ void mma_fp16(float* c, const unsigned* a, unsigned b0, unsigned b1) {
    asm volatile(
        "mma.sync.aligned.m16n8k16.row.col.f32.f16.f16.f32 "
        "{%0,%1,%2,%3}, {%4,%5,%6,%7}, {%8,%9}, {%0,%1,%2,%3};\n"
        : "+f"(c[0]), "+f"(c[1]), "+f"(c[2]), "+f"(c[3])
        : "r"(a[0]), "r"(a[1]), "r"(a[2]), "r"(a[3]), "r"(b0), "r"(b1));
}
__device__ __forceinline__ void ldsm4(unsigned* r, unsigned addr) {
    asm volatile("ldmatrix.sync.aligned.m8n8.x4.shared.b16 {%0,%1,%2,%3}, [%4];\n"
                 : "=r"(r[0]), "=r"(r[1]), "=r"(r[2]), "=r"(r[3]) : "r"(addr));
}
__device__ __forceinline__ void cp16(unsigned s, const void* g) {
    asm volatile("cp.async.cg.shared.global [%0],[%1],16;" :: "r"(s), "l"(g));
}
__device__ __forceinline__ float sigm(float x) { return 1.f / (1.f + __expf(-x)); }

// ---- legacy-MMA fp16 GEMM: C = Ah[128/CTA,K] @ Bh[BN,K]^T  (fp32 acc)
//      NWM warp-rows (warp tile (128/NWM) x 64), NWN = BN/64 warp-cols.
//      4-stage cp.async. epilogue: + bias + fut@Wt + Cin, then LSTM or store.
template<int BN, int NWM, bool LSTM>
__global__ void __launch_bounds__(32 * NWM * (BN / 64), 1)
gemm_leg(const fp16* __restrict__ Ah,
         const fp16* __restrict__ Bh, int K,
         const float* __restrict__ bias, const float* __restrict__ Wt, int Ntot,
         const float* __restrict__ fut,
         const float* __restrict__ Cin, long long ldcin,
         float* __restrict__ Cout, long long ldc,
         float* __restrict__ stc, float* __restrict__ sth,
         fp16* __restrict__ sthi)
{
    constexpr int NWN = BN / 64;                // warps along N
    constexpr int NT  = 32 * NWM * NWN;         // threads
    constexpr int MF  = 8 / NWM;                // 16-row m-fragments per warp
    constexpr int AST = 128 * 40;               // A elems per stage
    constexpr int BST = BN * 40;
    constexpr int STGB = (AST + BST) * 2;       // stage bytes
    constexpr int NCH  = 512 + 4 * BN;          // 16B chunks per stage

    extern __shared__ char dsm[];
    unsigned sb = (unsigned)__cvta_generic_to_shared(dsm);
    const int bm = blockIdx.y * 128, bn = blockIdx.x * BN;
    const int tid = threadIdx.x, warp = tid >> 5, lane = tid & 31;
    const int wm = (warp / NWN) * (16 * MF), wn = (warp % NWN) * 64;

    auto load = [&](int buf, int kt) {
        unsigned so = sb + buf * STGB;
        int k0 = kt * 32;
#pragma unroll
        for (int e = tid; e < NCH; e += NT) {
            const fp16* s; unsigned ro; int ci, base;
            if (e < 512) { s = Ah; ro = 0;       ci = e;       base = bm; }
            else         { s = Bh; ro = AST * 2; ci = e - 512; base = bn; }
            int row = ci >> 2, kc = ci & 3;
            cp16(so + ro + (unsigned)(row * 80 + kc * 16),
                 s + (size_t)(base + row) * K + k0 + kc * 8);
        }
        asm volatile("cp.async.commit_group;" ::: "memory");
    };

    float acc[MF][8][4];
#pragma unroll
    for (int i = 0; i < MF; i++)
#pragma unroll
        for (int j = 0; j < 8; j++)
#pragma unroll
            for (int e = 0; e < 4; e++) acc[i][j][e] = 0.f;

    const int T = K / 32;
    load(0, 0); load(1, 1); load(2, 2);

    for (int it = 0; it < T; ++it) {
        int rem = T - it;
        if (rem >= 3)      asm volatile("cp.async.wait_group 2;" ::: "memory");
        else if (rem == 2) asm volatile("cp.async.wait_group 1;" ::: "memory");
        else               asm volatile("cp.async.wait_group 0;" ::: "memory");
        __syncthreads();
        unsigned so = sb + (it & 3) * STGB;
#pragma unroll
        for (int ks = 0; ks < 2; ++ks) {
            const int kb = ks * 16;
            unsigned ah[MF][4], bh[8][2];
            const unsigned ak = (unsigned)((kb + ((lane & 16) ? 8 : 0)) * 2);
#pragma unroll
            for (int mf = 0; mf < MF; ++mf) {
                unsigned ad = so + (unsigned)((wm + mf * 16 + (lane & 15)) * 80) + ak;
                ldsm4(ah[mf], ad);
            }
            const unsigned brow = (unsigned)(((lane & 16) ? 8 : 0) + (lane & 7));
            const unsigned bk = (unsigned)((kb + ((lane & 8) ? 8 : 0)) * 2);
#pragma unroll
            for (int pp = 0; pp < 4; ++pp) {
                unsigned r[4];
                unsigned bd = so + AST * 2 + (unsigned)((wn + pp * 16 + brow) * 80) + bk;
                ldsm4(r, bd);
                bh[2*pp][0] = r[0];   bh[2*pp][1] = r[1];
                bh[2*pp+1][0] = r[2]; bh[2*pp+1][1] = r[3];
            }
#pragma unroll
            for (int mf = 0; mf < MF; ++mf)
#pragma unroll
                for (int nf = 0; nf < 8; ++nf)
                    mma_fp16(acc[mf][nf], ah[mf], bh[nf][0], bh[nf][1]);
        }
        if (it + 3 < T) load((it + 3) & 3, it + 3);
    }
    __syncthreads();

    // ---- epilogue: stage bias / Wt / fut into smem (overwrites stage bufs) ----
    float* bias_s = (float*)dsm;
    float* Wt_s   = bias_s + BN;
    float* fut_s  = Wt_s + Cc * BN;
    const bool wt = (Wt != nullptr);
    if (bias) for (int e = tid; e < BN; e += NT) bias_s[e] = bias[bn + e];
    if (wt) {
        for (int e = tid; e < Cc * BN; e += NT)
            Wt_s[e] = Wt[(size_t)(e / BN) * Ntot + bn + (e % BN)];
        for (int e = tid; e < 128 * Cc; e += NT)
            fut_s[e] = fut[(size_t)(bm + e / Cc) * Cc + (e % Cc)];
    }
    __syncthreads();

    const int c = lane & 3;
#pragma unroll
    for (int mf = 0; mf < MF; ++mf) {
        const int r0 = wm + mf * 16 + (lane >> 2);
        const long long rg0 = bm + r0;
#pragma unroll
        for (int nb = 0; nb < 8; ++nb) {
            const int cl = wn + nb * 8 + 2 * c;
            float* v = acc[mf][nb];
            if (bias) { float b0 = bias_s[cl], b1 = bias_s[cl+1]; v[0]+=b0; v[1]+=b1; v[2]+=b0; v[3]+=b1; }
            if (wt) {
#pragma unroll 1
                for (int k = 0; k < Cc; ++k) {
                    float w0 = Wt_s[k*BN+cl], w1 = Wt_s[k*BN+cl+1];
                    float fA = fut_s[r0*Cc+k], fB = fut_s[(r0+8)*Cc+k];
                    v[0] += fA*w0; v[1] += fA*w1; v[2] += fB*w0; v[3] += fB*w1;
                }
            }
            if (Cin) {
                float2 a0 = *(const float2*)(Cin + rg0*ldcin + bn + cl);
                float2 a1 = *(const float2*)(Cin + (rg0+8)*ldcin + bn + cl);
                v[0] += a0.x; v[1] += a0.y; v[2] += a1.x; v[3] += a1.y;
            }
            if (!LSTM) {
                *(float2*)(Cout + rg0*ldc + bn + cl)     = make_float2(v[0], v[1]);
                *(float2*)(Cout + (rg0+8)*ldc + bn + cl) = make_float2(v[2], v[3]);
            }
        }
        if (LSTM) {
#pragma unroll
            for (int q = 0; q < 4; ++q) {
                const int j = (((bn + wn + q*16) >> 4) << 2) + c;
#pragma unroll
                for (int e = 0; e < 2; ++e) {
                    long long rr = rg0 + e * 8;
                    float gi = acc[mf][2*q][2*e], gf = acc[mf][2*q][2*e+1];
                    float gg = acc[mf][2*q+1][2*e], go = acc[mf][2*q+1][2*e+1];
                    long long idx = rr * 2048 + j;
                    float cn = sigm(gf) * stc[idx] + sigm(gi) * tanhf(gg);
                    stc[idx] = cn;
                    float hv = sigm(go) * tanhf(cn);
                    sth[idx] = hv;
                    sthi[idx] = __float2half_rn(hv);
                }
            }
        }
    }
}

// ---- prep: natural -> gate-interleaved order ------------------------------
// within each 16-col group: i0 f0 i1 f1 i2 f2 i3 f3 g0 o0 g1 o1 g2 o2 g3 o3
__device__ __forceinline__ void imap(int n, int& gate, int& j) {
    int pos = n & 15, cc = (pos & 7) >> 1;
    gate = (pos < 8) ? (pos & 1) : (2 + (pos & 1));
    j = ((n >> 4) << 2) + cc;
}
__global__ void prep_iW(const float* __restrict__ W, int ldw, int Kd,
                        fp16* __restrict__ o)
{
    size_t total = (size_t)G4 * Kd;
    for (size_t i = blockIdx.x * (size_t)blockDim.x + threadIdx.x; i < total;
         i += (size_t)gridDim.x * blockDim.x) {
        int n = (int)(i / Kd), k = (int)(i - (size_t)n * Kd);
        int gate, j; imap(n, gate, j);
        o[i] = __float2half_rn(W[(size_t)(gate * 2048 + j) * ldw + k]);
    }
}
__global__ void prep_bias(const float* __restrict__ a, const float* __restrict__ b,
                          float* __restrict__ o)
{
    int n = blockIdx.x * blockDim.x + threadIdx.x;
    if (n >= G4) return;
    int gate, j; imap(n, gate, j);
    o[n] = a[gate * 2048 + j] + b[gate * 2048 + j];
}
__global__ void prep_Wt(const float* __restrict__ W, int ldw, int col0,
                        float* __restrict__ Wt)
{
    for (int i = blockIdx.x * blockDim.x + threadIdx.x; i < Cc * G4;
         i += gridDim.x * blockDim.x) {
        int k = i / G4, n = i - k * G4;
        int gate, j; imap(n, gate, j);
        Wt[i] = W[(size_t)(gate * 2048 + j) * ldw + col0 + k];
    }
}
__global__ void cvt_plain(const float* __restrict__ s, fp16* __restrict__ o, size_t n)
{
    for (size_t i = blockIdx.x * (size_t)blockDim.x + threadIdx.x; i < n;
         i += (size_t)gridDim.x * blockDim.x)
        o[i] = __float2half_rn(s[i]);
}

// ---- fut = h@trW^T + trb; also writes dec_scores[:, :, d, :] ----
__global__ void skinny_fut(const float* __restrict__ h, const float* __restrict__ trW,
                           const float* __restrict__ trb, float* __restrict__ fut,
                           float* __restrict__ outdec, int d)
{
    int warp = threadIdx.x >> 5, lane = threadIdx.x & 31;
    int r = blockIdx.x * 8 + warp;
    const float4* hr = (const float4*)(h + (size_t)r * 2048);
    float4 hv[16];
#pragma unroll
    for (int i = 0; i < 16; ++i) hv[i] = hr[i * 32 + lane];
#pragma unroll 1
    for (int n = 0; n < Cc; ++n) {
        const float4* wr = (const float4*)(trW + (size_t)n * 2048);
        float s = 0.f;
#pragma unroll
        for (int i = 0; i < 16; ++i) {
            float4 w = wr[i * 32 + lane];
            s += hv[i].x * w.x + hv[i].y * w.y + hv[i].z * w.z + hv[i].w * w.w;
        }
#pragma unroll
        for (int o = 16; o; o >>= 1) s += __shfl_down_sync(0xffffffffu, s, o);
        if (lane == 0) {
            float val = s + trb[n];
            fut[(size_t)r * Cc + n] = val;
            outdec[((size_t)r * Dd + d) * Cc + n] = val;
        }
    }
}
__global__ void cls_skinny(const float* __restrict__ eh, const float* __restrict__ W,
                           const float* __restrict__ b, float* __restrict__ out, int t)
{
    int w = (int)((blockIdx.x * (long long)blockDim.x + threadIdx.x) >> 5);
    int lane = threadIdx.x & 31;
    if (w >= Bb * Cc) return;
    int m = w / Cc, n = w - m * Cc;
    const float4* a = (const float4*)(eh + (size_t)m * 2048);
    const float4* ww = (const float4*)(W + (size_t)n * 2048);
    float s = 0.f;
#pragma unroll
    for (int i = 0; i < 16; ++i) {
        float4 av = a[i * 32 + lane], wv = ww[i * 32 + lane];
        s += av.x * wv.x + av.y * wv.y + av.z * wv.z + av.w * wv.w;
    }
#pragma unroll
    for (int o = 16; o; o >>= 1) s += __shfl_down_sync(0xffffffffu, s, o);
    if (lane == 0) out[((size_t)m * Tt + t) * Cc + n] = s + b[n];
}

extern "C" void kernel_launch(void* const* d_in, const int* in_sizes, int n_in,
                              void* d_out, int out_size)
{
    const float* x       = (const float*)d_in[0];
    const float* dec_Wih = (const float*)d_in[1];
    const float* dec_Whh = (const float*)d_in[2];
    const float* dec_bih = (const float*)d_in[3];
    const float* dec_bhh = (const float*)d_in[4];
    const float* tr_W    = (const float*)d_in[5];
    const float* tr_b    = (const float*)d_in[6];
    const float* enc_Wih = (const float*)d_in[7];
    const float* enc_Whh = (const float*)d_in[8];
    const float* enc_bih = (const float*)d_in[9];
    const float* enc_bhh = (const float*)d_in[10];
    const float* cls_W   = (const float*)d_in[11];
    const float* cls_b   = (const float*)d_in[12];
    float* out     = (float*)d_out;
    float* out_dec = out + (size_t)Bb * Tt * Cc;

    float *h, *c, *P, *fut, *eh, *ec, *dbias, *ebias, *Wtd, *Wte;
    fp16 *hh0, *hh1, *xh, *eh0, *eh1, *Wd, *Wi, *Wh;
    cudaGetSymbolAddress((void**)&h, g_h);     cudaGetSymbolAddress((void**)&c, g_c);
    cudaGetSymbolAddress((void**)&P, g_P);     cudaGetSymbolAddress((void**)&fut, g_fut);
    cudaGetSymbolAddress((void**)&eh, g_eh);   cudaGetSymbolAddress((void**)&ec, g_ec);
    cudaGetSymbolAddress((void**)&dbias, g_dbias); cudaGetSymbolAddress((void**)&ebias, g_ebias);
    cudaGetSymbolAddress((void**)&Wtd, g_Wtd); cudaGetSymbolAddress((void**)&Wte, g_Wte);
    cudaGetSymbolAddress((void**)&hh0, g_hh0); cudaGetSymbolAddress((void**)&hh1, g_hh1);
    cudaGetSymbolAddress((void**)&xh, g_xh);
    cudaGetSymbolAddress((void**)&eh0, g_eh0); cudaGetSymbolAddress((void**)&eh1, g_eh1);
    cudaGetSymbolAddress((void**)&Wd, g_Wd);   cudaGetSymbolAddress((void**)&Wi, g_Wi);
    cudaGetSymbolAddress((void**)&Wh, g_Wh);

    const int SMB = 4 * (128 * 40 + 128 * 40) * 2;   // 81920 (BN=128)
    const int SMS = 4 * (128 * 40 + 64 * 40) * 2;    // 61440 (BN=64)
    cudaFuncSetAttribute((const void*)gemm_leg<128, 2, true>,
                         cudaFuncAttributeMaxDynamicSharedMemorySize, SMB);
    cudaFuncSetAttribute((const void*)gemm_leg<128, 2, false>,
                         cudaFuncAttributeMaxDynamicSharedMemorySize, SMB);
    cudaFuncSetAttribute((const void*)gemm_leg<64, 4, true>,
                         cudaFuncAttributeMaxDynamicSharedMemorySize, SMS);

    cudaMemsetAsync(c,   0, sizeof(float) * (size_t)Rr * Ff, 0);
    cudaMemsetAsync(ec,  0, sizeof(float) * (size_t)Bb * Ff, 0);
    cudaMemsetAsync(eh0, 0, 2 * (size_t)Bb * Ff, 0);

    prep_bias<<<G4 / 256, 256>>>(dec_bih, dec_bhh, dbias);
    prep_bias<<<G4 / 256, 256>>>(enc_bih, enc_bhh, ebias);
    prep_Wt<<<704, 256>>>(dec_Wih, Cc, 0, Wtd);
    prep_Wt<<<704, 256>>>(enc_Wih, Ff + Cc, Ff, Wte);
    prep_iW<<<8192, 256>>>(dec_Whh, Ff, Ff, Wd);
    prep_iW<<<8192, 256>>>(enc_Whh, Ff, Ff, Wh);
    prep_iW<<<8192, 256>>>(enc_Wih, Ff + Cc, Ff, Wi);
    cvt_plain<<<8192, 256>>>(x, xh, (size_t)Rr * Ff);

    fp16* HH[2] = {hh0, hh1};

    // ---- Phase 1: 8 batched decoder steps (R=8192 rows), R12 config ----
    for (int d = 0; d < Dd; d++) {
        const fp16* Ahh = (d == 0) ? xh : HH[(d - 1) & 1];
        gemm_leg<128, 2, true><<<dim3(64, 64), 128, SMB>>>(
            Ahh, Wd, Ff,
            dbias, (d == 0) ? nullptr : Wtd, G4, fut,
            nullptr, 0, nullptr, 0,
            c, h, HH[d & 1]);
        skinny_fut<<<Rr / 8, 256>>>(h, tr_W, tr_b, fut, out_dec, d);
    }

    // ---- Phase 2: P = [x | fut] @ enc_Wih^T + ebias, R12 config ----
    gemm_leg<128, 2, false><<<dim3(64, 64), 128, SMB>>>(
        xh, Wi, Ff,
        ebias, Wte, G4, fut,
        nullptr, 0, P, (long long)G4,
        nullptr, nullptr, nullptr);

    fp16* EH[2] = {eh0, eh1};

    // ---- Phase 3: sequential encoder over T=64, NWM=4 (only change vs R12) ----
    for (int t = 0; t < Tt; t++) {
        gemm_leg<64, 4, true><<<dim3(128, 1), 128, SMS>>>(
            EH[t & 1], Wh, Ff,
            nullptr, nullptr, G4, nullptr,
            P + (size_t)t * G4, (long long)Tt * G4,
            nullptr, 0,
            ec, eh, EH[(t + 1) & 1]);
        cls_skinny<<<(Bb * Cc * 32 + 255) / 256, 256>>>(eh, cls_W, cls_b, out, t);
    }
}

// round 15
// speedup vs baseline: 1.1263x; 1.0103x over previous
#include <cuda_runtime.h>
#include <cuda_fp16.h>
#include <cstdint>
#include <math.h>

#define Bb 128
#define Tt 64
#define Ff 2048
#define Cc 22
#define Dd 8
#define Rr 8192
#define G4 8192
typedef __half fp16;

static __device__ float g_h [(size_t)Rr*Ff];
static __device__ float g_c [(size_t)Rr*Ff];
static __device__ float g_P [(size_t)Rr*G4];
static __device__ float g_fut[(size_t)Rr*Cc];
static __device__ float g_eh_all[(size_t)Tt*Bb*Ff];   // 64 MB: eh for every t
static __device__ float g_ec[(size_t)Bb*Ff];
static __device__ float g_dbias[G4], g_ebias[G4];
static __device__ float g_Wtd[Cc*G4], g_Wte[Cc*G4];
static __device__ fp16 g_hh0[(size_t)Rr*Ff];
static __device__ fp16 g_hh1[(size_t)Rr*Ff];
static __device__ fp16 g_xh [(size_t)Rr*Ff];
static __device__ fp16 g_eh0[(size_t)Bb*Ff];
static __device__ fp16 g_eh1[(size_t)Bb*Ff];
static __device__ fp16 g_Wd[(size_t)G4*Ff];
static __device__ fp16 g_Wi[(size_t)G4*Ff];
static __device__ fp16 g_Wh[(size_t)G4*Ff];

__device__ __forceinline__ void mma_fp16(float* c, const unsigned* a, unsigned b0, unsigned b1) {
    asm volatile(
        "mma.sync.aligned.m16n8k16.row.col.f32.f16.f16.f32 "
        "{%0,%1,%2,%3}, {%4,%5,%6,%7}, {%8,%9}, {%0,%1,%2,%3};\n"
        : "+f"(c[0]), "+f"(c[1]), "+f"(c[2]), "+f"(c[3])
        : "r"(a[0]), "r"(a[1]), "r"(a[2]), "r"(a[3]), "r"(b0), "r"(b1));
}
__device__ __forceinline__ void ldsm4(unsigned* r, unsigned addr) {
    asm volatile("ldmatrix.sync.aligned.m8n8.x4.shared.b16 {%0,%1,%2,%3}, [%4];\n"
                 : "=r"(r[0]), "=r"(r[1]), "=r"(r[2]), "=r"(r[3]) : "r"(addr));
}
__device__ __forceinline__ void cp16(unsigned s, const void* g) {
    asm volatile("cp.async.cg.shared.global [%0],[%1],16;" :: "r"(s), "l"(g));
}
__device__ __forceinline__ float sigm(float x) { return 1.f / (1.f + __expf(-x)); }

// ---- legacy-MMA fp16 GEMM: C = Ah[128/CTA,K] @ Bh[BN,K]^T  (fp32 acc)
//      NWM warp-rows (warp tile (128/NWM) x 64), NWN = BN/64 warp-cols.
//      4-stage cp.async. epilogue: + bias + fut@Wt + Cin, then LSTM or store.
template<int BN, int NWM, bool LSTM>
__global__ void __launch_bounds__(32 * NWM * (BN / 64), 1)
gemm_leg(const fp16* __restrict__ Ah,
         const fp16* __restrict__ Bh, int K,
         const float* __restrict__ bias, const float* __restrict__ Wt, int Ntot,
         const float* __restrict__ fut,
         const float* __restrict__ Cin, long long ldcin,
         float* __restrict__ Cout, long long ldc,
         float* __restrict__ stc, float* __restrict__ sth,
         fp16* __restrict__ sthi)
{
    constexpr int NWN = BN / 64;                // warps along N
    constexpr int NT  = 32 * NWM * NWN;         // threads
    constexpr int MF  = 8 / NWM;                // 16-row m-fragments per warp
    constexpr int AST = 128 * 40;               // A elems per stage
    constexpr int BST = BN * 40;
    constexpr int STGB = (AST + BST) * 2;       // stage bytes
    constexpr int NCH  = 512 + 4 * BN;          // 16B chunks per stage

    extern __shared__ char dsm[];
    unsigned sb = (unsigned)__cvta_generic_to_shared(dsm);
    const int bm = blockIdx.y * 128, bn = blockIdx.x * BN;
    const int tid = threadIdx.x, warp = tid >> 5, lane = tid & 31;
    const int wm = (warp / NWN) * (16 * MF), wn = (warp % NWN) * 64;

    auto load = [&](int buf, int kt) {
        unsigned so = sb + buf * STGB;
        int k0 = kt * 32;
#pragma unroll
        for (int e = tid; e < NCH; e += NT) {
            const fp16* s; unsigned ro; int ci, base;
            if (e < 512) { s = Ah; ro = 0;       ci = e;       base = bm; }
            else         { s = Bh; ro = AST * 2; ci = e - 512; base = bn; }
            int row = ci >> 2, kc = ci & 3;
            cp16(so + ro + (unsigned)(row * 80 + kc * 16),
                 s + (size_t)(base + row) * K + k0 + kc * 8);
        }
        asm volatile("cp.async.commit_group;" ::: "memory");
    };

    float acc[MF][8][4];
#pragma unroll
    for (int i = 0; i < MF; i++)
#pragma unroll
        for (int j = 0; j < 8; j++)
#pragma unroll
            for (int e = 0; e < 4; e++) acc[i][j][e] = 0.f;

    const int T = K / 32;
    load(0, 0); load(1, 1); load(2, 2);

    for (int it = 0; it < T; ++it) {
        int rem = T - it;
        if (rem >= 3)      asm volatile("cp.async.wait_group 2;" ::: "memory");
        else if (rem == 2) asm volatile("cp.async.wait_group 1;" ::: "memory");
        else               asm volatile("cp.async.wait_group 0;" ::: "memory");
        __syncthreads();
        unsigned so = sb + (it & 3) * STGB;
#pragma unroll
        for (int ks = 0; ks < 2; ++ks) {
            const int kb = ks * 16;
            unsigned ah[MF][4], bh[8][2];
            const unsigned ak = (unsigned)((kb + ((lane & 16) ? 8 : 0)) * 2);
#pragma unroll
            for (int mf = 0; mf < MF; ++mf) {
                unsigned ad = so + (unsigned)((wm + mf * 16 + (lane & 15)) * 80) + ak;
                ldsm4(ah[mf], ad);
            }
            const unsigned brow = (unsigned)(((lane & 16) ? 8 : 0) + (lane & 7));
            const unsigned bk = (unsigned)((kb + ((lane & 8) ? 8 : 0)) * 2);
#pragma unroll
            for (int pp = 0; pp < 4; ++pp) {
                unsigned r[4];
                unsigned bd = so + AST * 2 + (unsigned)((wn + pp * 16 + brow) * 80) + bk;
                ldsm4(r, bd);
                bh[2*pp][0] = r[0];   bh[2*pp][1] = r[1];
                bh[2*pp+1][0] = r[2]; bh[2*pp+1][1] = r[3];
            }
#pragma unroll
            for (int mf = 0; mf < MF; ++mf)
#pragma unroll
                for (int nf = 0; nf < 8; ++nf)
                    mma_fp16(acc[mf][nf], ah[mf], bh[nf][0], bh[nf][1]);
        }
        if (it + 3 < T) load((it + 3) & 3, it + 3);
    }
    __syncthreads();

    // ---- epilogue: stage bias / Wt / fut into smem (overwrites stage bufs) ----
    float* bias_s = (float*)dsm;
    float* Wt_s   = bias_s + BN;
    float* fut_s  = Wt_s + Cc * BN;
    const bool wt = (Wt != nullptr);
    if (bias) for (int e = tid; e < BN; e += NT) bias_s[e] = bias[bn + e];
    if (wt) {
        for (int e = tid; e < Cc * BN; e += NT)
            Wt_s[e] = Wt[(size_t)(e / BN) * Ntot + bn + (e % BN)];
        for (int e = tid; e < 128 * Cc; e += NT)
            fut_s[e] = fut[(size_t)(bm + e / Cc) * Cc + (e % Cc)];
    }
    __syncthreads();

    const int c = lane & 3;
#pragma unroll
    for (int mf = 0; mf < MF; ++mf) {
        const int r0 = wm + mf * 16 + (lane >> 2);
        const long long rg0 = bm + r0;
#pragma unroll
        for (int nb = 0; nb < 8; ++nb) {
            const int cl = wn + nb * 8 + 2 * c;
            float* v = acc[mf][nb];
            if (bias) { float b0 = bias_s[cl], b1 = bias_s[cl+1]; v[0]+=b0; v[1]+=b1; v[2]+=b0; v[3]+=b1; }
            if (wt) {
#pragma unroll 1
                for (int k = 0; k < Cc; ++k) {
                    float w0 = Wt_s[k*BN+cl], w1 = Wt_s[k*BN+cl+1];
                    float fA = fut_s[r0*Cc+k], fB = fut_s[(r0+8)*Cc+k];
                    v[0] += fA*w0; v[1] += fA*w1; v[2] += fB*w0; v[3] += fB*w1;
                }
            }
            if (Cin) {
                float2 a0 = *(const float2*)(Cin + rg0*ldcin + bn + cl);
                float2 a1 = *(const float2*)(Cin + (rg0+8)*ldcin + bn + cl);
                v[0] += a0.x; v[1] += a0.y; v[2] += a1.x; v[3] += a1.y;
            }
            if (!LSTM) {
                *(float2*)(Cout + rg0*ldc + bn + cl)     = make_float2(v[0], v[1]);
                *(float2*)(Cout + (rg0+8)*ldc + bn + cl) = make_float2(v[2], v[3]);
            }
        }
        if (LSTM) {
#pragma unroll
            for (int q = 0; q < 4; ++q) {
                const int j = (((bn + wn + q*16) >> 4) << 2) + c;
#pragma unroll
                for (int e = 0; e < 2; ++e) {
                    long long rr = rg0 + e * 8;
                    float gi = acc[mf][2*q][2*e], gf = acc[mf][2*q][2*e+1];
                    float gg = acc[mf][2*q+1][2*e], go = acc[mf][2*q+1][2*e+1];
                    long long idx = rr * 2048 + j;
                    float cn = sigm(gf) * stc[idx] + sigm(gi) * tanhf(gg);
                    stc[idx] = cn;
                    float hv = sigm(go) * tanhf(cn);
                    sth[idx] = hv;
                    sthi[idx] = __float2half_rn(hv);
                }
            }
        }
    }
}

// ---- prep: natural -> gate-interleaved order ------------------------------
// within each 16-col group: i0 f0 i1 f1 i2 f2 i3 f3 g0 o0 g1 o1 g2 o2 g3 o3
__device__ __forceinline__ void imap(int n, int& gate, int& j) {
    int pos = n & 15, cc = (pos & 7) >> 1;
    gate = (pos < 8) ? (pos & 1) : (2 + (pos & 1));
    j = ((n >> 4) << 2) + cc;
}
__global__ void prep_iW(const float* __restrict__ W, int ldw, int Kd,
                        fp16* __restrict__ o)
{
    size_t total = (size_t)G4 * Kd;
    for (size_t i = blockIdx.x * (size_t)blockDim.x + threadIdx.x; i < total;
         i += (size_t)gridDim.x * blockDim.x) {
        int n = (int)(i / Kd), k = (int)(i - (size_t)n * Kd);
        int gate, j; imap(n, gate, j);
        o[i] = __float2half_rn(W[(size_t)(gate * 2048 + j) * ldw + k]);
    }
}
__global__ void prep_bias(const float* __restrict__ a, const float* __restrict__ b,
                          float* __restrict__ o)
{
    int n = blockIdx.x * blockDim.x + threadIdx.x;
    if (n >= G4) return;
    int gate, j; imap(n, gate, j);
    o[n] = a[gate * 2048 + j] + b[gate * 2048 + j];
}
__global__ void prep_Wt(const float* __restrict__ W, int ldw, int col0,
                        float* __restrict__ Wt)
{
    for (int i = blockIdx.x * blockDim.x + threadIdx.x; i < Cc * G4;
         i += gridDim.x * blockDim.x) {
        int k = i / G4, n = i - k * G4;
        int gate, j; imap(n, gate, j);
        Wt[i] = W[(size_t)(gate * 2048 + j) * ldw + col0 + k];
    }
}
__global__ void cvt_plain(const float* __restrict__ s, fp16* __restrict__ o, size_t n)
{
    for (size_t i = blockIdx.x * (size_t)blockDim.x + threadIdx.x; i < n;
         i += (size_t)gridDim.x * blockDim.x)
        o[i] = __float2half_rn(s[i]);
}

// ---- fut = h@trW^T + trb; also writes dec_scores[:, :, d, :] ----
__global__ void skinny_fut(const float* __restrict__ h, const float* __restrict__ trW,
                           const float* __restrict__ trb, float* __restrict__ fut,
                           float* __restrict__ outdec, int d)
{
    int warp = threadIdx.x >> 5, lane = threadIdx.x & 31;
    int r = blockIdx.x * 8 + warp;
    const float4* hr = (const float4*)(h + (size_t)r * 2048);
    float4 hv[16];
#pragma unroll
    for (int i = 0; i < 16; ++i) hv[i] = hr[i * 32 + lane];
#pragma unroll 1
    for (int n = 0; n < Cc; ++n) {
        const float4* wr = (const float4*)(trW + (size_t)n * 2048);
        float s = 0.f;
#pragma unroll
        for (int i = 0; i < 16; ++i) {
            float4 w = wr[i * 32 + lane];
            s += hv[i].x * w.x + hv[i].y * w.y + hv[i].z * w.z + hv[i].w * w.w;
        }
#pragma unroll
        for (int o = 16; o; o >>= 1) s += __shfl_down_sync(0xffffffffu, s, o);
        if (lane == 0) {
            float val = s + trb[n];
            fut[(size_t)r * Cc + n] = val;
            outdec[((size_t)r * Dd + d) * Cc + n] = val;
        }
    }
}

// ---- batched classifier: enc_scores[b,t,:] = eh_all[t,b,:]@cls_W^T + cls_b --
__global__ void cls_all(const float* __restrict__ eh_all, const float* __restrict__ W,
                        const float* __restrict__ b, float* __restrict__ out)
{
    int warp = threadIdx.x >> 5, lane = threadIdx.x & 31;
    int r = blockIdx.x * 8 + warp;                 // r = t*128 + b
    int t = r >> 7, bi = r & 127;
    const float4* a = (const float4*)(eh_all + (size_t)r * 2048);
    float4 hv[16];
#pragma unroll
    for (int i = 0; i < 16; ++i) hv[i] = a[i * 32 + lane];
#pragma unroll 1
    for (int n = 0; n < Cc; ++n) {
        const float4* ww = (const float4*)(W + (size_t)n * 2048);
        float s = 0.f;
#pragma unroll
        for (int i = 0; i < 16; ++i) {
            float4 w = ww[i * 32 + lane];
            s += hv[i].x * w.x + hv[i].y * w.y + hv[i].z * w.z + hv[i].w * w.w;
        }
#pragma unroll
        for (int o = 16; o; o >>= 1) s += __shfl_down_sync(0xffffffffu, s, o);
        if (lane == 0) out[((size_t)bi * Tt + t) * Cc + n] = s + b[n];
    }
}

extern "C" void kernel_launch(void* const* d_in, const int* in_sizes, int n_in,
                              void* d_out, int out_size)
{
    const float* x       = (const float*)d_in[0];
    const float* dec_Wih = (const float*)d_in[1];
    const float* dec_Whh = (const float*)d_in[2];
    const float* dec_bih = (const float*)d_in[3];
    const float* dec_bhh = (const float*)d_in[4];
    const float* tr_W    = (const float*)d_in[5];
    const float* tr_b    = (const float*)d_in[6];
    const float* enc_Wih = (const float*)d_in[7];
    const float* enc_Whh = (const float*)d_in[8];
    const float* enc_bih = (const float*)d_in[9];
    const float* enc_bhh = (const float*)d_in[10];
    const float* cls_W   = (const float*)d_in[11];
    const float* cls_b   = (const float*)d_in[12];
    float* out     = (float*)d_out;
    float* out_dec = out + (size_t)Bb * Tt * Cc;

    float *h, *c, *P, *fut, *eh_all, *ec, *dbias, *ebias, *Wtd, *Wte;
    fp16 *hh0, *hh1, *xh, *eh0, *eh1, *Wd, *Wi, *Wh;
    cudaGetSymbolAddress((void**)&h, g_h);     cudaGetSymbolAddress((void**)&c, g_c);
    cudaGetSymbolAddress((void**)&P, g_P);     cudaGetSymbolAddress((void**)&fut, g_fut);
    cudaGetSymbolAddress((void**)&eh_all, g_eh_all);
    cudaGetSymbolAddress((void**)&ec, g_ec);
    cudaGetSymbolAddress((void**)&dbias, g_dbias); cudaGetSymbolAddress((void**)&ebias, g_ebias);
    cudaGetSymbolAddress((void**)&Wtd, g_Wtd); cudaGetSymbolAddress((void**)&Wte, g_Wte);
    cudaGetSymbolAddress((void**)&hh0, g_hh0); cudaGetSymbolAddress((void**)&hh1, g_hh1);
    cudaGetSymbolAddress((void**)&xh, g_xh);
    cudaGetSymbolAddress((void**)&eh0, g_eh0); cudaGetSymbolAddress((void**)&eh1, g_eh1);
    cudaGetSymbolAddress((void**)&Wd, g_Wd);   cudaGetSymbolAddress((void**)&Wi, g_Wi);
    cudaGetSymbolAddress((void**)&Wh, g_Wh);

    const int SMB = 4 * (128 * 40 + 128 * 40) * 2;   // 81920 (BN=128)
    const int SMS = 4 * (128 * 40 + 64 * 40) * 2;    // 61440 (BN=64)
    cudaFuncSetAttribute((const void*)gemm_leg<128, 2, true>,
                         cudaFuncAttributeMaxDynamicSharedMemorySize, SMB);
    cudaFuncSetAttribute((const void*)gemm_leg<128, 2, false>,
                         cudaFuncAttributeMaxDynamicSharedMemorySize, SMB);
    cudaFuncSetAttribute((const void*)gemm_leg<64, 4, true>,
                         cudaFuncAttributeMaxDynamicSharedMemorySize, SMS);

    cudaMemsetAsync(c,   0, sizeof(float) * (size_t)Rr * Ff, 0);
    cudaMemsetAsync(ec,  0, sizeof(float) * (size_t)Bb * Ff, 0);
    cudaMemsetAsync(eh0, 0, 2 * (size_t)Bb * Ff, 0);

    prep_bias<<<G4 / 256, 256>>>(dec_bih, dec_bhh, dbias);
    prep_bias<<<G4 / 256, 256>>>(enc_bih, enc_bhh, ebias);
    prep_Wt<<<704, 256>>>(dec_Wih, Cc, 0, Wtd);
    prep_Wt<<<704, 256>>>(enc_Wih, Ff + Cc, Ff, Wte);
    prep_iW<<<8192, 256>>>(dec_Whh, Ff, Ff, Wd);
    prep_iW<<<8192, 256>>>(enc_Whh, Ff, Ff, Wh);
    prep_iW<<<8192, 256>>>(enc_Wih, Ff + Cc, Ff, Wi);
    cvt_plain<<<8192, 256>>>(x, xh, (size_t)Rr * Ff);

    fp16* HH[2] = {hh0, hh1};

    // ---- Phase 1: 8 batched decoder steps (R=8192 rows) ----
    for (int d = 0; d < Dd; d++) {
        const fp16* Ahh = (d == 0) ? xh : HH[(d - 1) & 1];
        gemm_leg<128, 2, true><<<dim3(64, 64), 128, SMB>>>(
            Ahh, Wd, Ff,
            dbias, (d == 0) ? nullptr : Wtd, G4, fut,
            nullptr, 0, nullptr, 0,
            c, h, HH[d & 1]);
        skinny_fut<<<Rr / 8, 256>>>(h, tr_W, tr_b, fut, out_dec, d);
    }

    // ---- Phase 2: P = [x | fut] @ enc_Wih^T + ebias (interleaved cols) ----
    gemm_leg<128, 2, false><<<dim3(64, 64), 128, SMB>>>(
        xh, Wi, Ff,
        ebias, Wte, G4, fut,
        nullptr, 0, P, (long long)G4,
        nullptr, nullptr, nullptr);

    fp16* EH[2] = {eh0, eh1};

    // ---- Phase 3: sequential encoder over T=64; eh(t) saved, cls deferred ----
    for (int t = 0; t < Tt; t++) {
        gemm_leg<64, 4, true><<<dim3(128, 1), 128, SMS>>>(
            EH[t & 1], Wh, Ff,
            nullptr, nullptr, G4, nullptr,
            P + (size_t)t * G4, (long long)Tt * G4,
            nullptr, 0,
            ec, eh_all + (size_t)t * Bb * Ff, EH[(t + 1) & 1]);
    }

    // ---- Deferred classifier: one batched kernel for all (b,t) ----
    cls_all<<<(Tt * Bb) / 8, 256>>>(eh_all, cls_W, cls_b, out);
}

// round 16
// speedup vs baseline: 1.3826x; 1.2275x over previous
#include <cuda_runtime.h>
#include <cuda_fp16.h>
#include <cstdint>
#include <math.h>

#define Bb 128
#define Tt 64
#define Ff 2048
#define Cc 22
#define Dd 8
#define Rr 8192
#define G4 8192
typedef __half fp16;

static __device__ float g_h [(size_t)Rr*Ff];
static __device__ float g_c [(size_t)Rr*Ff];
static __device__ float g_P [(size_t)Rr*G4];
static __device__ float g_fut[(size_t)Rr*Cc];
static __device__ float g_eh_all[(size_t)Tt*Bb*Ff];
static __device__ float g_ec[(size_t)Bb*Ff];
static __device__ float g_Wtd[Cc*G4], g_Wte[Cc*G4];     // (unused fp32 kept out)
static __device__ fp16 g_futh[(size_t)Rr*32];           // fut padded to 32 (col22=1)
static __device__ fp16 g_WQd[(size_t)G4*32];            // dec: Wt cols + bias row
static __device__ fp16 g_WQe[(size_t)G4*32];            // enc: Wt cols + bias row
static __device__ fp16 g_hh0[(size_t)Rr*Ff];
static __device__ fp16 g_hh1[(size_t)Rr*Ff];
static __device__ fp16 g_xh [(size_t)Rr*Ff];
static __device__ fp16 g_eh0[(size_t)Bb*Ff];
static __device__ fp16 g_eh1[(size_t)Bb*Ff];
static __device__ fp16 g_Wd[(size_t)G4*Ff];
static __device__ fp16 g_Wi[(size_t)G4*Ff];
static __device__ fp16 g_Wh[(size_t)G4*Ff];

__device__ __forceinline__ void mma_fp16(float* c, const unsigned* a, unsigned b0, unsigned b1) {
    asm volatile(
        "mma.sync.aligned.m16n8k16.row.col.f32.f16.f16.f32 "
        "{%0,%1,%2,%3}, {%4,%5,%6,%7}, {%8,%9}, {%0,%1,%2,%3};\n"
        : "+f"(c[0]), "+f"(c[1]), "+f"(c[2]), "+f"(c[3])
        : "r"(a[0]), "r"(a[1]), "r"(a[2]), "r"(a[3]), "r"(b0), "r"(b1));
}
__device__ __forceinline__ void ldsm4(unsigned* r, unsigned addr) {
    asm volatile("ldmatrix.sync.aligned.m8n8.x4.shared.b16 {%0,%1,%2,%3}, [%4];\n"
                 : "=r"(r[0]), "=r"(r[1]), "=r"(r[2]), "=r"(r[3]) : "r"(addr));
}
__device__ __forceinline__ void cp16(unsigned s, const void* g) {
    asm volatile("cp.async.cg.shared.global [%0],[%1],16;" :: "r"(s), "l"(g));
}
__device__ __forceinline__ float sigm(float x) { return 1.f / (1.f + __expf(-x)); }

// ---- legacy-MMA fp16 GEMM: C = Ah[128/CTA,K] @ Bh[BN,K]^T (+ Aq@Bq^T K=32) ---
//      NWM warp-rows, NWN = BN/64 warp-cols, 4-stage cp.async.
//      HASQ: extra K-tile carries fut@Wt + bias on the tensor pipe.
template<int BN, int NWM, bool LSTM, bool HASQ>
__global__ void __launch_bounds__(32 * NWM * (BN / 64), 1)
gemm_leg(const fp16* __restrict__ Ah,
         const fp16* __restrict__ Bh, int K,
         const fp16* __restrict__ Aq, const fp16* __restrict__ Bq,
         const float* __restrict__ Cin, long long ldcin,
         float* __restrict__ Cout, long long ldc,
         float* __restrict__ stc, float* __restrict__ sth,
         fp16* __restrict__ sthi)
{
    constexpr int NWN = BN / 64;
    constexpr int NT  = 32 * NWM * NWN;
    constexpr int MF  = 8 / NWM;
    constexpr int AST = 128 * 40;
    constexpr int BST = BN * 40;
    constexpr int STGB = (AST + BST) * 2;
    constexpr int NCH  = 512 + 4 * BN;

    extern __shared__ char dsm[];
    unsigned sb = (unsigned)__cvta_generic_to_shared(dsm);
    const int bm = blockIdx.y * 128, bn = blockIdx.x * BN;
    const int tid = threadIdx.x, warp = tid >> 5, lane = tid & 31;
    const int wm = (warp / NWN) * (16 * MF), wn = (warp % NWN) * 64;

    const int T = K / 32;
    const int TT = T + (HASQ ? 1 : 0);

    auto load = [&](int buf, int kt) {
        unsigned so = sb + buf * STGB;
        if (!HASQ || kt < T) {
            int k0 = kt * 32;
#pragma unroll
            for (int e = tid; e < NCH; e += NT) {
                const fp16* s; unsigned ro; int ci, base;
                if (e < 512) { s = Ah; ro = 0;       ci = e;       base = bm; }
                else         { s = Bh; ro = AST * 2; ci = e - 512; base = bn; }
                int row = ci >> 2, kc = ci & 3;
                cp16(so + ro + (unsigned)(row * 80 + kc * 16),
                     s + (size_t)(base + row) * K + k0 + kc * 8);
            }
        } else {
#pragma unroll
            for (int e = tid; e < NCH; e += NT) {
                const fp16* s; unsigned ro; int ci, base;
                if (e < 512) { s = Aq; ro = 0;       ci = e;       base = bm; }
                else         { s = Bq; ro = AST * 2; ci = e - 512; base = bn; }
                int row = ci >> 2, kc = ci & 3;
                cp16(so + ro + (unsigned)(row * 80 + kc * 16),
                     s + (size_t)(base + row) * 32 + kc * 8);
            }
        }
        asm volatile("cp.async.commit_group;" ::: "memory");
    };

    float acc[MF][8][4];
#pragma unroll
    for (int i = 0; i < MF; i++)
#pragma unroll
        for (int j = 0; j < 8; j++)
#pragma unroll
            for (int e = 0; e < 4; e++) acc[i][j][e] = 0.f;

    load(0, 0); load(1, 1); load(2, 2);

    for (int it = 0; it < TT; ++it) {
        int rem = TT - it;
        if (rem >= 3)      asm volatile("cp.async.wait_group 2;" ::: "memory");
        else if (rem == 2) asm volatile("cp.async.wait_group 1;" ::: "memory");
        else               asm volatile("cp.async.wait_group 0;" ::: "memory");
        __syncthreads();
        unsigned so = sb + (it & 3) * STGB;
#pragma unroll
        for (int ks = 0; ks < 2; ++ks) {
            const int kb = ks * 16;
            unsigned ah[MF][4], bh[8][2];
            const unsigned ak = (unsigned)((kb + ((lane & 16) ? 8 : 0)) * 2);
#pragma unroll
            for (int mf = 0; mf < MF; ++mf) {
                unsigned ad = so + (unsigned)((wm + mf * 16 + (lane & 15)) * 80) + ak;
                ldsm4(ah[mf], ad);
            }
            const unsigned brow = (unsigned)(((lane & 16) ? 8 : 0) + (lane & 7));
            const unsigned bk = (unsigned)((kb + ((lane & 8) ? 8 : 0)) * 2);
#pragma unroll
            for (int pp = 0; pp < 4; ++pp) {
                unsigned r[4];
                unsigned bd = so + AST * 2 + (unsigned)((wn + pp * 16 + brow) * 80) + bk;
                ldsm4(r, bd);
                bh[2*pp][0] = r[0];   bh[2*pp][1] = r[1];
                bh[2*pp+1][0] = r[2]; bh[2*pp+1][1] = r[3];
            }
#pragma unroll
            for (int mf = 0; mf < MF; ++mf)
#pragma unroll
                for (int nf = 0; nf < 8; ++nf)
                    mma_fp16(acc[mf][nf], ah[mf], bh[nf][0], bh[nf][1]);
        }
        if (it + 3 < TT) load((it + 3) & 3, it + 3);
    }

    // ---- epilogue (no scalar fut/bias work anymore) ----
    const int c = lane & 3;
#pragma unroll
    for (int mf = 0; mf < MF; ++mf) {
        const int r0 = wm + mf * 16 + (lane >> 2);
        const long long rg0 = bm + r0;
#pragma unroll
        for (int nb = 0; nb < 8; ++nb) {
            const int cl = wn + nb * 8 + 2 * c;
            float* v = acc[mf][nb];
            if (Cin) {
                float2 a0 = *(const float2*)(Cin + rg0*ldcin + bn + cl);
                float2 a1 = *(const float2*)(Cin + (rg0+8)*ldcin + bn + cl);
                v[0] += a0.x; v[1] += a0.y; v[2] += a1.x; v[3] += a1.y;
            }
            if (!LSTM) {
                *(float2*)(Cout + rg0*ldc + bn + cl)     = make_float2(v[0], v[1]);
                *(float2*)(Cout + (rg0+8)*ldc + bn + cl) = make_float2(v[2], v[3]);
            }
        }
        if (LSTM) {
#pragma unroll
            for (int q = 0; q < 4; ++q) {
                const int j = (((bn + wn + q*16) >> 4) << 2) + c;
#pragma unroll
                for (int e = 0; e < 2; ++e) {
                    long long rr = rg0 + e * 8;
                    float gi = acc[mf][2*q][2*e], gf = acc[mf][2*q][2*e+1];
                    float gg = acc[mf][2*q+1][2*e], go = acc[mf][2*q+1][2*e+1];
                    long long idx = rr * 2048 + j;
                    float cn = sigm(gf) * stc[idx] + sigm(gi) * tanhf(gg);
                    stc[idx] = cn;
                    float hv = sigm(go) * tanhf(cn);
                    sth[idx] = hv;
                    sthi[idx] = __float2half_rn(hv);
                }
            }
        }
    }
}

// ---- prep: natural -> gate-interleaved order ------------------------------
__device__ __forceinline__ void imap(int n, int& gate, int& j) {
    int pos = n & 15, cc = (pos & 7) >> 1;
    gate = (pos < 8) ? (pos & 1) : (2 + (pos & 1));
    j = ((n >> 4) << 2) + cc;
}
__global__ void prep_iW(const float* __restrict__ W, int ldw, int Kd,
                        fp16* __restrict__ o)
{
    size_t total = (size_t)G4 * Kd;
    for (size_t i = blockIdx.x * (size_t)blockDim.x + threadIdx.x; i < total;
         i += (size_t)gridDim.x * blockDim.x) {
        int n = (int)(i / Kd), k = (int)(i - (size_t)n * Kd);
        int gate, j; imap(n, gate, j);
        o[i] = __float2half_rn(W[(size_t)(gate * 2048 + j) * ldw + k]);
    }
}
// WQ[n*32+k]: k<22 -> W[gate_row][col0+k]; k==22 -> bias; else 0  (fp16)
__global__ void prep_WQ(const float* __restrict__ W, int ldw, int col0,
                        const float* __restrict__ ba, const float* __restrict__ bb,
                        fp16* __restrict__ o)
{
    for (int i = blockIdx.x * blockDim.x + threadIdx.x; i < G4 * 32;
         i += gridDim.x * blockDim.x) {
        int n = i >> 5, k = i & 31;
        int gate, j; imap(n, gate, j);
        float v = 0.f;
        if (k < Cc)       v = W[(size_t)(gate * 2048 + j) * ldw + col0 + k];
        else if (k == Cc) v = ba[gate * 2048 + j] + bb[gate * 2048 + j];
        o[i] = __float2half_rn(v);
    }
}
__global__ void futh_init(fp16* __restrict__ futh)
{
    int i = blockIdx.x * blockDim.x + threadIdx.x;
    if (i >= Rr * 32) return;
    futh[i] = __float2half_rn(((i & 31) == Cc) ? 1.f : 0.f);
}
__global__ void cvt_plain(const float* __restrict__ s, fp16* __restrict__ o, size_t n)
{
    for (size_t i = blockIdx.x * (size_t)blockDim.x + threadIdx.x; i < n;
         i += (size_t)gridDim.x * blockDim.x)
        o[i] = __float2half_rn(s[i]);
}

// ---- fut = h@trW^T + trb; writes fp32 fut (unused), fp16 futh, dec_scores --
__global__ void skinny_fut(const float* __restrict__ h, const float* __restrict__ trW,
                           const float* __restrict__ trb, fp16* __restrict__ futh,
                           float* __restrict__ outdec, int d)
{
    int warp = threadIdx.x >> 5, lane = threadIdx.x & 31;
    int r = blockIdx.x * 8 + warp;
    const float4* hr = (const float4*)(h + (size_t)r * 2048);
    float4 hv[16];
#pragma unroll
    for (int i = 0; i < 16; ++i) hv[i] = hr[i * 32 + lane];
#pragma unroll 1
    for (int n = 0; n < Cc; ++n) {
        const float4* wr = (const float4*)(trW + (size_t)n * 2048);
        float s = 0.f;
#pragma unroll
        for (int i = 0; i < 16; ++i) {
            float4 w = wr[i * 32 + lane];
            s += hv[i].x * w.x + hv[i].y * w.y + hv[i].z * w.z + hv[i].w * w.w;
        }
#pragma unroll
        for (int o = 16; o; o >>= 1) s += __shfl_down_sync(0xffffffffu, s, o);
        if (lane == 0) {
            float val = s + trb[n];
            futh[(size_t)r * 32 + n] = __float2half_rn(val);
            outdec[((size_t)r * Dd + d) * Cc + n] = val;
        }
    }
}

// ---- batched classifier ----------------------------------------------------
__global__ void cls_all(const float* __restrict__ eh_all, const float* __restrict__ W,
                        const float* __restrict__ b, float* __restrict__ out)
{
    int warp = threadIdx.x >> 5, lane = threadIdx.x & 31;
    int r = blockIdx.x * 8 + warp;
    int t = r >> 7, bi = r & 127;
    const float4* a = (const float4*)(eh_all + (size_t)r * 2048);
    float4 hv[16];
#pragma unroll
    for (int i = 0; i < 16; ++i) hv[i] = a[i * 32 + lane];
#pragma unroll 1
    for (int n = 0; n < Cc; ++n) {
        const float4* ww = (const float4*)(W + (size_t)n * 2048);
        float s = 0.f;
#pragma unroll
        for (int i = 0; i < 16; ++i) {
            float4 w = ww[i * 32 + lane];
            s += hv[i].x * w.x + hv[i].y * w.y + hv[i].z * w.z + hv[i].w * w.w;
        }
#pragma unroll
        for (int o = 16; o; o >>= 1) s += __shfl_down_sync(0xffffffffu, s, o);
        if (lane == 0) out[((size_t)bi * Tt + t) * Cc + n] = s + b[n];
    }
}

extern "C" void kernel_launch(void* const* d_in, const int* in_sizes, int n_in,
                              void* d_out, int out_size)
{
    const float* x       = (const float*)d_in[0];
    const float* dec_Wih = (const float*)d_in[1];
    const float* dec_Whh = (const float*)d_in[2];
    const float* dec_bih = (const float*)d_in[3];
    const float* dec_bhh = (const float*)d_in[4];
    const float* tr_W    = (const float*)d_in[5];
    const float* tr_b    = (const float*)d_in[6];
    const float* enc_Wih = (const float*)d_in[7];
    const float* enc_Whh = (const float*)d_in[8];
    const float* enc_bih = (const float*)d_in[9];
    const float* enc_bhh = (const float*)d_in[10];
    const float* cls_W   = (const float*)d_in[11];
    const float* cls_b   = (const float*)d_in[12];
    float* out     = (float*)d_out;
    float* out_dec = out + (size_t)Bb * Tt * Cc;

    float *h, *c, *P, *eh_all, *ec;
    fp16 *futh, *WQd, *WQe, *hh0, *hh1, *xh, *eh0, *eh1, *Wd, *Wi, *Wh;
    cudaGetSymbolAddress((void**)&h, g_h);     cudaGetSymbolAddress((void**)&c, g_c);
    cudaGetSymbolAddress((void**)&P, g_P);
    cudaGetSymbolAddress((void**)&eh_all, g_eh_all);
    cudaGetSymbolAddress((void**)&ec, g_ec);
    cudaGetSymbolAddress((void**)&futh, g_futh);
    cudaGetSymbolAddress((void**)&WQd, g_WQd); cudaGetSymbolAddress((void**)&WQe, g_WQe);
    cudaGetSymbolAddress((void**)&hh0, g_hh0); cudaGetSymbolAddress((void**)&hh1, g_hh1);
    cudaGetSymbolAddress((void**)&xh, g_xh);
    cudaGetSymbolAddress((void**)&eh0, g_eh0); cudaGetSymbolAddress((void**)&eh1, g_eh1);
    cudaGetSymbolAddress((void**)&Wd, g_Wd);   cudaGetSymbolAddress((void**)&Wi, g_Wi);
    cudaGetSymbolAddress((void**)&Wh, g_Wh);

    const int SMB = 4 * (128 * 40 + 128 * 40) * 2;   // 81920 (BN=128)
    const int SMS = 4 * (128 * 40 + 64 * 40) * 2;    // 61440 (BN=64)
    cudaFuncSetAttribute((const void*)gemm_leg<128, 2, true, true>,
                         cudaFuncAttributeMaxDynamicSharedMemorySize, SMB);
    cudaFuncSetAttribute((const void*)gemm_leg<128, 2, false, true>,
                         cudaFuncAttributeMaxDynamicSharedMemorySize, SMB);
    cudaFuncSetAttribute((const void*)gemm_leg<64, 4, true, false>,
                         cudaFuncAttributeMaxDynamicSharedMemorySize, SMS);

    cudaMemsetAsync(c,   0, sizeof(float) * (size_t)Rr * Ff, 0);
    cudaMemsetAsync(ec,  0, sizeof(float) * (size_t)Bb * Ff, 0);
    cudaMemsetAsync(eh0, 0, 2 * (size_t)Bb * Ff, 0);

    futh_init<<<(Rr * 32 + 255) / 256, 256>>>(futh);
    prep_WQ<<<1024, 256>>>(dec_Wih, Cc, 0, dec_bih, dec_bhh, WQd);
    prep_WQ<<<1024, 256>>>(enc_Wih, Ff + Cc, Ff, enc_bih, enc_bhh, WQe);
    prep_iW<<<8192, 256>>>(dec_Whh, Ff, Ff, Wd);
    prep_iW<<<8192, 256>>>(enc_Whh, Ff, Ff, Wh);
    prep_iW<<<8192, 256>>>(enc_Wih, Ff + Cc, Ff, Wi);
    cvt_plain<<<8192, 256>>>(x, xh, (size_t)Rr * Ff);

    fp16* HH[2] = {hh0, hh1};

    // ---- Phase 1: 8 batched decoder steps (fut term via extra K-tile) ----
    for (int d = 0; d < Dd; d++) {
        const fp16* Ahh = (d == 0) ? xh : HH[(d - 1) & 1];
        gemm_leg<128, 2, true, true><<<dim3(64, 64), 128, SMB>>>(
            Ahh, Wd, Ff,
            futh, WQd,
            nullptr, 0, nullptr, 0,
            c, h, HH[d & 1]);
        skinny_fut<<<Rr / 8, 256>>>(h, tr_W, tr_b, futh, out_dec, d);
    }

    // ---- Phase 2: P = [x | fut] @ enc_Wih^T + ebias ----
    gemm_leg<128, 2, false, true><<<dim3(64, 64), 128, SMB>>>(
        xh, Wi, Ff,
        futh, WQe,
        nullptr, 0, P, (long long)G4,
        nullptr, nullptr, nullptr);

    fp16* EH[2] = {eh0, eh1};

    // ---- Phase 3: sequential encoder over T=64; cls deferred ----
    for (int t = 0; t < Tt; t++) {
        gemm_leg<64, 4, true, false><<<dim3(128, 1), 128, SMS>>>(
            EH[t & 1], Wh, Ff,
            nullptr, nullptr,
            P + (size_t)t * G4, (long long)Tt * G4,
            nullptr, 0,
            ec, eh_all + (size_t)t * Bb * Ff, EH[(t + 1) & 1]);
    }

    // ---- Deferred classifier ----
    cls_all<<<(Tt * Bb) / 8, 256>>>(eh_all, cls_W, cls_b, out);
}